// round 6
// baseline (speedup 1.0000x reference)
#include <cuda_runtime.h>

#define BATCH 32
#define LC 512
#define LQ 64
#define DIM 1024

typedef unsigned long long u64;

__device__ __forceinline__ u64 ffma2(u64 a, u64 b, u64 c) {
    u64 d;
    asm("fma.rn.f32x2 %0, %1, %2, %3;" : "=l"(d) : "l"(a), "l"(b), "l"(c));
    return d;
}
__device__ __forceinline__ u64 pack2(float x, float y) {
    u64 d;
    asm("mov.b64 %0, {%1, %2};" : "=l"(d) : "f"(x), "f"(y));
    return d;
}
__device__ __forceinline__ float2 unpack2(u64 v) {
    float2 r;
    asm("mov.b64 {%0, %1}, %2;" : "=f"(r.x), "=f"(r.y) : "l"(v));
    return r;
}
__device__ __forceinline__ float pairsum(u64 v) {
    float2 r = unpack2(v);
    return r.x + r.y;
}
__device__ __forceinline__ void cp16(unsigned saddr, const void* gaddr) {
    asm volatile("cp.async.cg.shared.global [%0], [%1], 16;"
                 :: "r"(saddr), "l"(gaddr) : "memory");
}
#define CP_COMMIT() asm volatile("cp.async.commit_group;" ::: "memory")
#define CP_WAIT1()  asm volatile("cp.async.wait_group 1;" ::: "memory")

// ---------------- scratch -----------------------------------------------------
__device__ float g_s0[BATCH * LC];              // c @ proj_c
__device__ float g_s1[BATCH * LQ];              // q @ proj_q
__device__ float g_qs[BATCH * LQ * DIM];        // q * proj_cq (8 MiB)
__device__ float g_simp[2][BATCH * LC * LQ];    // split-K partials (8 MiB)
__device__ float g_sim[BATCH * LC * LQ];        // similarity matrix (4 MiB)
__device__ float g_m[BATCH * LC];               // rowmax of sim over q
__device__ float g_q2c[BATCH * DIM];            // query-to-context vector

// ---------------- K0: projections + scaled q + zero q2c ---------------------
__global__ void k_pre(const float* __restrict__ c, const float* __restrict__ q,
                      const float* __restrict__ pc, const float* __restrict__ pq,
                      const float* __restrict__ pcq) {
    int gtid = blockIdx.x * blockDim.x + threadIdx.x;
    if (gtid < BATCH * DIM) g_q2c[gtid] = 0.f;

    int warp = gtid >> 5;
    int lane = threadIdx.x & 31;
    const int NC = BATCH * LC;
    if (warp < NC) {
        const float* src = c + (size_t)warp * DIM;
        float s = 0.f;
#pragma unroll
        for (int i = 0; i < 8; i++) {
            int k = (lane + i * 32) * 4;
            float4 v = *(const float4*)(src + k);
            float4 p = *(const float4*)(pc + k);
            s += v.x * p.x + v.y * p.y + v.z * p.z + v.w * p.w;
        }
#pragma unroll
        for (int o = 16; o; o >>= 1) s += __shfl_xor_sync(0xffffffffu, s, o);
        if (lane == 0) g_s0[warp] = s;
    } else if (warp < NC + BATCH * LQ) {
        int r = warp - NC;
        const float* src = q + (size_t)r * DIM;
        float* dst = g_qs + (size_t)r * DIM;
        float s = 0.f;
#pragma unroll
        for (int i = 0; i < 8; i++) {
            int k = (lane + i * 32) * 4;
            float4 v  = *(const float4*)(src + k);
            float4 pp = *(const float4*)(pq + k);
            s += v.x * pp.x + v.y * pp.y + v.z * pp.z + v.w * pp.w;
            float4 pv = *(const float4*)(pcq + k);
            float4 o = {v.x * pv.x, v.y * pv.y, v.z * pv.z, v.w * pv.w};
            *(float4*)(dst + k) = o;
        }
#pragma unroll
        for (int o = 16; o; o >>= 1) s += __shfl_xor_sync(0xffffffffu, s, o);
        if (lane == 0) g_s1[r] = s;
    }
}

// ---------------- K1: split-K sim GEMM partials ------------------------------
// grid (LC/64, 2, BATCH) = 512 blocks. tile 64x64, 128 threads,
// micro 8(m)x4(n) f32x2 K-pairs, cp.async double buffer. K-half = 512.
#define KT 32
#define KH (DIM / 2)
#define AW 36
__global__ void __launch_bounds__(128, 4)
k_sim(const float* __restrict__ c) {
    __shared__ __align__(16) float As[2][64][AW];   // 18 KB
    __shared__ __align__(16) float Bs[2][64][AW];   // 18 KB

    int cm = blockIdx.x, kh = blockIdx.y, b = blockIdx.z;
    int tl = threadIdx.x;
    int tx = tl & 15;          // n-thread
    int ty = tl >> 4;          // m-thread (0..7)

    const float* cA = c + ((size_t)b * LC + cm * 64) * DIM + kh * KH;
    const float* cB = g_qs + (size_t)b * LQ * DIM + kh * KH;

    int lrow = tl >> 1;                 // 0..63
    int lhalf = (tl & 1) * 16;
    unsigned sa0 = (unsigned)__cvta_generic_to_shared(&As[0][lrow][lhalf]);
    unsigned sb0 = (unsigned)__cvta_generic_to_shared(&Bs[0][lrow][lhalf]);
    const unsigned PP = 64 * AW * 4;
    const float* gA = cA + (size_t)lrow * DIM + lhalf;
    const float* gB = cB + (size_t)lrow * DIM + lhalf;

    u64 acc[8][4];
#pragma unroll
    for (int i = 0; i < 8; i++)
#pragma unroll
        for (int j = 0; j < 4; j++) acc[i][j] = 0ull;

#pragma unroll
    for (int j = 0; j < 4; j++) {
        cp16(sa0 + j * 16, gA + j * 4);
        cp16(sb0 + j * 16, gB + j * 4);
    }
    CP_COMMIT();

    for (int it = 0; it < KH / KT; it++) {
        int nit = (it + 1 < KH / KT) ? it + 1 : it;
        unsigned nb = (it + 1) & 1;
#pragma unroll
        for (int j = 0; j < 4; j++) {
            cp16(sa0 + nb * PP + j * 16, gA + nit * KT + j * 4);
            cp16(sb0 + nb * PP + j * 16, gB + nit * KT + j * 4);
        }
        CP_COMMIT();
        CP_WAIT1();
        __syncthreads();

        int pp = it & 1;
#pragma unroll
        for (int kk2 = 0; kk2 < KT / 2; kk2++) {
            u64 am[8], bn[4];
#pragma unroll
            for (int i = 0; i < 8; i++)
                am[i] = *(const u64*)&As[pp][ty + 8 * i][2 * kk2];
#pragma unroll
            for (int j = 0; j < 4; j++)
                bn[j] = *(const u64*)&Bs[pp][tx + 16 * j][2 * kk2];
#pragma unroll
            for (int i = 0; i < 8; i++)
#pragma unroll
                for (int j = 0; j < 4; j++)
                    acc[i][j] = ffma2(am[i], bn[j], acc[i][j]);
        }
        __syncthreads();
    }

    // write partial sums (no epilogue math; k_fix combines)
    float* dst = &g_simp[kh][((size_t)b * LC + cm * 64) * LQ];
#pragma unroll
    for (int i = 0; i < 8; i++) {
        int m = ty + 8 * i;
#pragma unroll
        for (int j = 0; j < 4; j++)
            dst[(size_t)m * LQ + tx + 16 * j] = pairsum(acc[i][j]);
    }
}

// ---------------- K1b: combine K-halves, add s0+s1, rowmax -------------------
// one warp per c-row; grid 2048 x 256 threads
__global__ void k_fix() {
    int gw = (blockIdx.x * blockDim.x + threadIdx.x) >> 5;
    int lane = threadIdx.x & 31;
    int b = gw >> 9;
    size_t base = (size_t)gw * LQ;
    float s0 = g_s0[gw];
    float v0 = g_simp[0][base + lane] + g_simp[1][base + lane]
             + s0 + g_s1[b * LQ + lane];
    float v1 = g_simp[0][base + lane + 32] + g_simp[1][base + lane + 32]
             + s0 + g_s1[b * LQ + lane + 32];
    float rm = fmaxf(v0, v1);
#pragma unroll
    for (int o = 16; o; o >>= 1) rm = fmaxf(rm, __shfl_xor_sync(0xffffffffu, rm, o));
    g_sim[base + lane] = v0;
    g_sim[base + lane + 32] = v1;
    if (lane == 0) g_m[gw] = rm;
}

// ---------------- K2: q2c[b,:] = softmax_c(m) @ c[b] ------------------------
__global__ void k_q2c(const float* __restrict__ c) {
    __shared__ float wm[LC];
    __shared__ float red[256];
    int b = blockIdx.y, cb = blockIdx.x;
    int t = threadIdx.x;
    float v0 = g_m[b * LC + t];
    float v1 = g_m[b * LC + 256 + t];
    red[t] = fmaxf(v0, v1);
    __syncthreads();
#pragma unroll
    for (int s = 128; s > 0; s >>= 1) {
        if (t < s) red[t] = fmaxf(red[t], red[t + s]);
        __syncthreads();
    }
    float mx = red[0];
    __syncthreads();
    float e0 = expf(v0 - mx), e1 = expf(v1 - mx);
    wm[t] = e0;
    wm[t + 256] = e1;
    red[t] = e0 + e1;
    __syncthreads();
#pragma unroll
    for (int s = 128; s > 0; s >>= 1) {
        if (t < s) red[t] += red[t + s];
        __syncthreads();
    }
    float inv = 1.f / red[0];
    __syncthreads();

    float4 acc = {0.f, 0.f, 0.f, 0.f};
    const float* cb0 = c + ((size_t)b * LC + cb * 16) * DIM + (t << 2);
#pragma unroll
    for (int cr = 0; cr < 16; cr++) {
        float w = wm[cb * 16 + cr] * inv;
        float4 cv = *(const float4*)(cb0 + (size_t)cr * DIM);
        acc.x = fmaf(w, cv.x, acc.x);
        acc.y = fmaf(w, cv.y, acc.y);
        acc.z = fmaf(w, cv.z, acc.z);
        acc.w = fmaf(w, cv.w, acc.w);
    }
    float* dst = g_q2c + b * DIM + (t << 2);
    atomicAdd(dst + 0, acc.x);
    atomicAdd(dst + 1, acc.y);
    atomicAdd(dst + 2, acc.z);
    atomicAdd(dst + 3, acc.w);
}

// ---------------- K3: softmax rows, c2q = a @ q, fused output ----------------
// grid (LC/RT, 2, BATCH) = 512 blocks; each block: 64 rows x 512 d-cols.
// Padded a_sT (stride 66) — conflict-light stores, broadcast reads, no ALU.
#define RT 64
#define DC 128
#define DHALF 512
__global__ void __launch_bounds__(256, 3)
k_out(const float* __restrict__ c, const float* __restrict__ q,
      float* __restrict__ out) {
    __shared__ __align__(16) float a_sT[LQ][RT + 2];   // [qq][r] ~16.9 KB
    __shared__ __align__(16) float q_s[LQ][DC];        // 32 KB
    int ct = blockIdx.x, dh = blockIdx.y, b = blockIdx.z;
    int t = threadIdx.x;
    int warp = t >> 5, lane = t & 31;

    // row softmax from stored rowmax; transposed store (2-way conflicts max)
#pragma unroll
    for (int i = 0; i < 8; i++) {
        int r = warp * 8 + i;
        int row = ct * RT + r;
        size_t sbase = ((size_t)b * LC + row) * LQ;
        float m = g_m[b * LC + row];
        float v0 = expf(g_sim[sbase + lane] - m);
        float v1 = expf(g_sim[sbase + lane + 32] - m);
        float s = v0 + v1;
#pragma unroll
        for (int o = 16; o; o >>= 1) s += __shfl_xor_sync(0xffffffffu, s, o);
        float inv = 1.f / s;
        a_sT[lane][r] = v0 * inv;
        a_sT[lane + 32][r] = v1 * inv;
    }
    __syncthreads();

    const float* qb = q + (size_t)b * LQ * DIM;
    int rbase = warp * 8;        // 4 row-pairs per warp

    for (int dc = dh * DHALF; dc < dh * DHALF + DHALF; dc += DC) {
#pragma unroll
        for (int i = 0; i < 8; i++) {
            int idx = t + i * 256;
            int qr = idx >> 5;
            int qc = (idx & 31) << 2;
            *(float4*)&q_s[qr][qc] = *(const float4*)(qb + (size_t)qr * DIM + dc + qc);
        }
        __syncthreads();

        u64 acc[4][4];
#pragma unroll
        for (int p = 0; p < 4; p++)
#pragma unroll
            for (int d = 0; d < 4; d++) acc[p][d] = 0ull;

#pragma unroll 8
        for (int qq = 0; qq < LQ; qq++) {
            float4 qv = *(const float4*)&q_s[qq][lane << 2];
            u64 qd[4] = {pack2(qv.x, qv.x), pack2(qv.y, qv.y),
                         pack2(qv.z, qv.z), pack2(qv.w, qv.w)};
            u64 ar[4];
#pragma unroll
            for (int p = 0; p < 4; p++)
                ar[p] = *(const u64*)&a_sT[qq][rbase + 2 * p];
#pragma unroll
            for (int p = 0; p < 4; p++)
#pragma unroll
                for (int d = 0; d < 4; d++)
                    acc[p][d] = ffma2(ar[p], qd[d], acc[p][d]);
        }

        int d0 = dc + (lane << 2);
        float4 qc4 = *(const float4*)(g_q2c + b * DIM + d0);
#pragma unroll
        for (int p = 0; p < 4; p++) {
            float2 u0 = unpack2(acc[p][0]);
            float2 u1 = unpack2(acc[p][1]);
            float2 u2 = unpack2(acc[p][2]);
            float2 u3 = unpack2(acc[p][3]);
            float4 arow[2] = {{u0.x, u1.x, u2.x, u3.x}, {u0.y, u1.y, u2.y, u3.y}};
#pragma unroll
            for (int e = 0; e < 2; e++) {
                int row = ct * RT + rbase + 2 * p + e;
                float4 a4 = arow[e];
                float4 cv = *(const float4*)(c + ((size_t)b * LC + row) * DIM + d0);
                float* ob = out + ((size_t)b * LC + row) * (4 * DIM) + d0;
                *(float4*)(ob) = cv;
                *(float4*)(ob + DIM) = a4;
                float4 t2 = {cv.x * qc4.x, cv.y * qc4.y, cv.z * qc4.z, cv.w * qc4.w};
                *(float4*)(ob + 2 * DIM) = t2;
                float4 t3 = {cv.x * a4.x, cv.y * a4.y, cv.z * a4.z, cv.w * a4.w};
                *(float4*)(ob + 3 * DIM) = t3;
            }
        }
        __syncthreads();
    }
}

// ---------------- launch -----------------------------------------------------
extern "C" void kernel_launch(void* const* d_in, const int* in_sizes, int n_in,
                              void* d_out, int out_size) {
    const float* c   = (const float*)d_in[0];
    const float* q   = (const float*)d_in[1];
    const float* pc  = (const float*)d_in[2];
    const float* pq  = (const float*)d_in[3];
    const float* pcq = (const float*)d_in[4];
    float* out = (float*)d_out;
    (void)in_sizes; (void)n_in; (void)out_size;

    k_pre<<<BATCH * (LC + LQ) * 32 / 256, 256>>>(c, q, pc, pq, pcq);
    k_sim<<<dim3(LC / 64, 2, BATCH), 128>>>(c);
    k_fix<<<BATCH * LC * 32 / 256, 256>>>();
    k_q2c<<<dim3(32, BATCH), 256>>>(c);
    k_out<<<dim3(LC / RT, 2, BATCH), 256>>>(c, q, out);
}